// round 12
// baseline (speedup 1.0000x reference)
#include <cuda_runtime.h>
#include <cuda_fp16.h>
#include <cstdint>

#define IN_DIM 128
#define OUT_DIM 64
#define MAXN 50000
#define MAXE 1600000
#define SLOPE 0.1f
#define EPS 1e-12f
#define SCAN_BLK 1024
#define MAX_SCAN_BLOCKS 64

// Scratch (static device globals — allocation is forbidden). Zero-init at load.
__device__ __align__(256) __half g_newh[MAXN * OUT_DIM]; // transformed features, fp16
__device__ float  g_ssrc[MAXN];          // new[n] . a_src
__device__ float  g_sdst[MAXN];          // new[n] . a_dst
__device__ int    g_cnt[MAXN];           // out-degree histogram (zeroed by k_aggregate)
__device__ int    g_base[MAXN];          // CSR offsets (mutated by k_place into end[])
__device__ int    g_csr[MAXE];           // src-sorted dst indices (4B payload)
__device__ int    g_bsum[MAX_SCAN_BLOCKS];
__device__ int    g_flag[MAX_SCAN_BLOCKS];

// ---------------------------------------------------------------------------
// Kernel 1 (fused): blocks [0, nbT): transform new = x@W^T+b -> fp16, scores.
//   2 THREADS PER NODE (each owns 32 of 64 output dims) -> 392 transform
//   blocks instead of 196: fixes the 1.32-blocks/SM wave quantization that
//   made the transform run at 2x its balanced FFMA floor.
//   Blocks [nbT, ...): histogram of src. Block 0 zeroes scan flags.
// ---------------------------------------------------------------------------
__global__ __launch_bounds__(256) void k_fused(
    const float* __restrict__ x, const float* __restrict__ W,
    const float* __restrict__ b, const float* __restrict__ a,
    const int* __restrict__ eidx, int nN, int nE, int nbT)
{
    if ((int)blockIdx.x >= nbT) {
        // ---- histogram part ----
        int tidg   = (blockIdx.x - nbT) * blockDim.x + threadIdx.x;
        int stride = (gridDim.x - nbT) * blockDim.x;
        for (int e = tidg; e < nE; e += stride) {
            int s = eidx[e];
            s = min(max(s, 0), nN - 1);
            atomicAdd(&g_cnt[s], 1);
        }
        return;
    }

    // ---- transform part ----
    if (blockIdx.x == 0 && threadIdx.x < MAX_SCAN_BLOCKS) g_flag[threadIdx.x] = 0;

    __shared__ __align__(16) float sW[OUT_DIM * IN_DIM];
    __shared__ float sb[OUT_DIM], sas[OUT_DIM], sad[OUT_DIM];
    for (int i = threadIdx.x; i < OUT_DIM * IN_DIM; i += blockDim.x) sW[i] = W[i];
    if (threadIdx.x < OUT_DIM) {
        sb[threadIdx.x]  = b[threadIdx.x];
        sas[threadIdx.x] = a[threadIdx.x];
        sad[threadIdx.x] = a[OUT_DIM + threadIdx.x];
    }
    __syncthreads();

    int tid = threadIdx.x;
    int n   = blockIdx.x * 128 + (tid >> 1);   // 128 nodes per block
    int h   = tid & 1;                         // output-dim half
    int d0  = h * 32;
    if (n >= nN) return;

    const float4* __restrict__ x4 = (const float4*)(x + (size_t)n * IN_DIM);
    const float4* __restrict__ W4 = (const float4*)sW;   // W4[d*32 + kk]

    float acc[32];
#pragma unroll
    for (int j = 0; j < 32; j++) acc[j] = 0.f;

    for (int kk = 0; kk < IN_DIM / 4; kk++) {
        float4 xv = x4[kk];   // lane pairs share the row -> 16 lines/LDG
#pragma unroll
        for (int j = 0; j < 32; j++) {
            float4 wv = W4[(d0 + j) * (IN_DIM / 4) + kk];  // 2-addr broadcast
            acc[j] += xv.x * wv.x + xv.y * wv.y + xv.z * wv.z + xv.w * wv.w;
        }
    }

    float ss = 0.f, sd = 0.f;
    uint2* newh = (uint2*)(g_newh + ((size_t)n << 6) + d0);
#pragma unroll
    for (int j = 0; j < 8; j++) {
        float v0 = acc[4*j+0] + sb[d0 + 4*j+0];
        float v1 = acc[4*j+1] + sb[d0 + 4*j+1];
        float v2 = acc[4*j+2] + sb[d0 + 4*j+2];
        float v3 = acc[4*j+3] + sb[d0 + 4*j+3];
        __half2 h0 = __float22half2_rn(make_float2(v0, v1));
        __half2 h1 = __float22half2_rn(make_float2(v2, v3));
        uint2 hv;
        hv.x = *(unsigned int*)&h0;
        hv.y = *(unsigned int*)&h1;
        newh[j] = hv;
        ss += v0*sas[d0+4*j+0] + v1*sas[d0+4*j+1] + v2*sas[d0+4*j+2] + v3*sas[d0+4*j+3];
        sd += v0*sad[d0+4*j+0] + v1*sad[d0+4*j+1] + v2*sad[d0+4*j+2] + v3*sad[d0+4*j+3];
    }
    // combine the two halves of the node's score
    ss += __shfl_xor_sync(0xFFFFFFFF, ss, 1);
    sd += __shfl_xor_sync(0xFFFFFFFF, sd, 1);
    if (h == 0) {
        g_ssrc[n] = ss;
        g_sdst[n] = sd;
    }
}

// ---------------------------------------------------------------------------
// Kernel 2: exclusive scan of g_cnt -> g_base, decoupled lookback.
// ---------------------------------------------------------------------------
__global__ __launch_bounds__(SCAN_BLK) void k_scan(int nN)
{
    __shared__ int swarp[32];
    __shared__ int s_total;
    __shared__ int s_boff;
    int tid  = threadIdx.x;
    int lane = tid & 31;
    int wid  = tid >> 5;
    int bid  = blockIdx.x;
    int i    = bid * SCAN_BLK + tid;

    int v = (i < nN) ? g_cnt[i] : 0;

    int inc = v;
#pragma unroll
    for (int off = 1; off < 32; off <<= 1) {
        int t = __shfl_up_sync(0xFFFFFFFF, inc, off);
        if (lane >= off) inc += t;
    }
    if (lane == 31) swarp[wid] = inc;
    __syncthreads();
    if (wid == 0) {
        int wv = swarp[lane];
        int winc = wv;
#pragma unroll
        for (int off = 1; off < 32; off <<= 1) {
            int t = __shfl_up_sync(0xFFFFFFFF, winc, off);
            if (lane >= off) winc += t;
        }
        swarp[lane] = winc - wv;
    }
    __syncthreads();
    int incl = swarp[wid] + inc;
    if (tid == SCAN_BLK - 1) s_total = incl;
    __syncthreads();

    if (tid == 0) {
        g_bsum[bid] = s_total;
        __threadfence();
        *(volatile int*)&g_flag[bid] = 1;
    }

    if (wid == 0) {
        int off = 0;
        for (int base = 0; base < bid; base += 32) {
            int j = base + lane;
            int vj = 0;
            if (j < bid) {
                while (*(volatile int*)&g_flag[j] == 0) {}
                __threadfence();
                vj = *(volatile int*)&g_bsum[j];
            }
#pragma unroll
            for (int o = 16; o > 0; o >>= 1)
                vj += __shfl_down_sync(0xFFFFFFFF, vj, o);
            off += __shfl_sync(0xFFFFFFFF, vj, 0);
        }
        if (lane == 0) s_boff = off;
    }
    __syncthreads();

    if (i < nN) g_base[i] = s_boff + incl - v;
}

// ---------------------------------------------------------------------------
// Kernel 3: place dst (4B) into CSR slot — no gathers, no exp here.
// Cursor atomic leaves g_base[n] == end[n].
// ---------------------------------------------------------------------------
__global__ __launch_bounds__(256) void k_place(
    const int* __restrict__ eidx, int nE, int nN)
{
    int e = blockIdx.x * blockDim.x + threadIdx.x;
    if (e >= nE) return;
    int s = eidx[e];
    int d = eidx[(size_t)nE + e];
    s = min(max(s, 0), nN - 1);
    d = min(max(d, 0), nN - 1);
    int pos = atomicAdd(&g_base[s], 1);
    g_csr[pos] = d;
}

// ---------------------------------------------------------------------------
// Kernel 4: gather-aggregate + normalize. 8 lanes/node, lane c owns 16B of
// the fp16 row. Score/exp recomputed here (issued once per warp-inst, so the
// 8-lane redundancy is free); sdst[dst] is a broadcast load within a group.
// Unrolled x4 for MLP. Re-zeroes g_cnt for replay.
// ---------------------------------------------------------------------------
__global__ __launch_bounds__(256) void k_aggregate(
    float* __restrict__ out, int nN)
{
    int n = blockIdx.x * 32 + (threadIdx.x >> 3);
    int c = threadIdx.x & 7;
    if (n >= nN) return;

    int beg = (n == 0) ? 0 : g_base[n - 1];
    int end = g_base[n];
    float ssn = g_ssrc[n];

    float acc[8];
#pragma unroll
    for (int j = 0; j < 8; j++) acc[j] = 0.f;
    float rs = 0.f;

    int i = beg;
    for (; i + 4 <= end; i += 4) {
        int dst0 = g_csr[i];
        int dst1 = g_csr[i + 1];
        int dst2 = g_csr[i + 2];
        int dst3 = g_csr[i + 3];
        float sd0 = g_sdst[dst0];
        float sd1 = g_sdst[dst1];
        float sd2 = g_sdst[dst2];
        float sd3 = g_sdst[dst3];
        uint4 h0 = *(const uint4*)(g_newh + ((size_t)dst0 << 6) + c * 8);
        uint4 h1 = *(const uint4*)(g_newh + ((size_t)dst1 << 6) + c * 8);
        uint4 h2 = *(const uint4*)(g_newh + ((size_t)dst2 << 6) + c * 8);
        uint4 h3 = *(const uint4*)(g_newh + ((size_t)dst3 << 6) + c * 8);
        float sc0 = ssn + sd0;  sc0 = sc0 > 0.f ? sc0 : SLOPE * sc0;
        float sc1 = ssn + sd1;  sc1 = sc1 > 0.f ? sc1 : SLOPE * sc1;
        float sc2 = ssn + sd2;  sc2 = sc2 > 0.f ? sc2 : SLOPE * sc2;
        float sc3 = ssn + sd3;  sc3 = sc3 > 0.f ? sc3 : SLOPE * sc3;
        float ev0 = __expf(sc0);
        float ev1 = __expf(sc1);
        float ev2 = __expf(sc2);
        float ev3 = __expf(sc3);
#pragma unroll
        for (int q = 0; q < 4; q++) {
            float ev = (q == 0) ? ev0 : (q == 1) ? ev1 : (q == 2) ? ev2 : ev3;
            uint4 hv = (q == 0) ? h0 : (q == 1) ? h1 : (q == 2) ? h2 : h3;
            float2 f0 = __half22float2(*(__half2*)&hv.x);
            float2 f1 = __half22float2(*(__half2*)&hv.y);
            float2 f2 = __half22float2(*(__half2*)&hv.z);
            float2 f3 = __half22float2(*(__half2*)&hv.w);
            acc[0] += ev * f0.x;  acc[1] += ev * f0.y;
            acc[2] += ev * f1.x;  acc[3] += ev * f1.y;
            acc[4] += ev * f2.x;  acc[5] += ev * f2.y;
            acc[6] += ev * f3.x;  acc[7] += ev * f3.y;
            rs += ev;
        }
    }
    for (; i < end; i++) {
        int dst = g_csr[i];
        float sc = ssn + g_sdst[dst];
        sc = sc > 0.f ? sc : SLOPE * sc;
        float ev = __expf(sc);
        uint4 hv = *(const uint4*)(g_newh + ((size_t)dst << 6) + c * 8);
        float2 f0 = __half22float2(*(__half2*)&hv.x);
        float2 f1 = __half22float2(*(__half2*)&hv.y);
        float2 f2 = __half22float2(*(__half2*)&hv.z);
        float2 f3 = __half22float2(*(__half2*)&hv.w);
        acc[0] += ev * f0.x;  acc[1] += ev * f0.y;
        acc[2] += ev * f1.x;  acc[3] += ev * f1.y;
        acc[4] += ev * f2.x;  acc[5] += ev * f2.y;
        acc[6] += ev * f3.x;  acc[7] += ev * f3.y;
        rs += ev;
    }

    float inv = 1.f / (rs + EPS);
    float* op = out + ((size_t)n << 6) + c * 8;
    *(float4*)op       = make_float4(acc[0]*inv, acc[1]*inv, acc[2]*inv, acc[3]*inv);
    *(float4*)(op + 4) = make_float4(acc[4]*inv, acc[5]*inv, acc[6]*inv, acc[7]*inv);

    if (c == 0) g_cnt[n] = 0;   // clean for next launch (graph replay)
}

// ---------------------------------------------------------------------------
extern "C" void kernel_launch(void* const* d_in, const int* in_sizes, int n_in,
                              void* d_out, int out_size)
{
    const float* x    = (const float*)d_in[0];
    const int*   eidx = (const int*)d_in[1];    // int32 (JAX x64 disabled)
    const float* W    = (const float*)d_in[2];
    const float* b    = (const float*)d_in[3];
    const float* a    = (const float*)d_in[4];
    float* out = (float*)d_out;

    int nN = in_sizes[0] / IN_DIM;   // 50000
    int nE = in_sizes[1] / 2;        // 1600000

    int nbT = (nN * 2 + 255) / 256;   // 391 transform blocks (128 nodes each)
    int nbH = 1024;
    k_fused<<<nbT + nbH, 256>>>(x, W, b, a, eidx, nN, nE, nbT);

    int nbS = (nN + SCAN_BLK - 1) / SCAN_BLK;     // 49
    k_scan<<<nbS, SCAN_BLK>>>(nN);

    k_place<<<(nE + 255) / 256, 256>>>(eidx, nE, nN);

    k_aggregate<<<(nN + 31) / 32, 256>>>(out, nN);
}

// round 13
// speedup vs baseline: 1.0786x; 1.0786x over previous
#include <cuda_runtime.h>
#include <cuda_fp16.h>
#include <cstdint>

#define IN_DIM 128
#define OUT_DIM 64
#define MAXN 50000
#define MAXE 1600000
#define SLOPE 0.1f
#define EPS 1e-12f
#define SCAN_BLK 1024
#define MAX_SCAN_BLOCKS 64

// Scratch (static device globals — allocation is forbidden). Zero-init at load.
__device__ __align__(256) __half g_newh[MAXN * OUT_DIM]; // transformed features, fp16
__device__ float  g_ssrc[MAXN];          // new[n] . a_src
__device__ float  g_sdst[MAXN];          // new[n] . a_dst
__device__ int    g_cnt[MAXN];           // out-degree histogram (zeroed by k_aggregate)
__device__ int    g_base[MAXN];          // CSR offsets (mutated by k_place into end[])
__device__ int    g_csr[MAXE];           // src-sorted dst indices (4B payload)
__device__ int    g_bsum[MAX_SCAN_BLOCKS];
__device__ int    g_flag[MAX_SCAN_BLOCKS];

// ---------------------------------------------------------------------------
// Kernel 1 (fused): blocks [0, nbT): transform new = x@W^T+b -> fp16, scores.
//   ONE node per thread (warp-uniform W broadcast — proven inner loop), but
//   128-thread blocks -> 391 transform blocks: fixes the 196-block wave
//   quantization (1.32 blk/SM -> 2.64) without touching the hot loop.
//   Blocks [nbT, ...): histogram of src. Block 0 zeroes scan flags.
// ---------------------------------------------------------------------------
__global__ __launch_bounds__(128) void k_fused(
    const float* __restrict__ x, const float* __restrict__ W,
    const float* __restrict__ b, const float* __restrict__ a,
    const int* __restrict__ eidx, int nN, int nE, int nbT)
{
    if ((int)blockIdx.x >= nbT) {
        // ---- histogram part ----
        int tidg   = (blockIdx.x - nbT) * blockDim.x + threadIdx.x;
        int stride = (gridDim.x - nbT) * blockDim.x;
        for (int e = tidg; e < nE; e += stride) {
            int s = eidx[e];
            s = min(max(s, 0), nN - 1);
            atomicAdd(&g_cnt[s], 1);
        }
        return;
    }

    // ---- transform part ----
    if (blockIdx.x == 0 && threadIdx.x < MAX_SCAN_BLOCKS) g_flag[threadIdx.x] = 0;

    __shared__ __align__(16) float sW[OUT_DIM * IN_DIM];
    __shared__ float sb[OUT_DIM], sas[OUT_DIM], sad[OUT_DIM];
    for (int i = threadIdx.x; i < OUT_DIM * IN_DIM; i += blockDim.x) sW[i] = W[i];
    if (threadIdx.x < OUT_DIM) {
        sb[threadIdx.x]  = b[threadIdx.x];
        sas[threadIdx.x] = a[threadIdx.x];
        sad[threadIdx.x] = a[OUT_DIM + threadIdx.x];
    }
    __syncthreads();

    int n = blockIdx.x * blockDim.x + threadIdx.x;
    if (n >= nN) return;

    const float4* __restrict__ x4 = (const float4*)(x + (size_t)n * IN_DIM);
    const float4* __restrict__ W4 = (const float4*)sW;

    float acc[OUT_DIM];
#pragma unroll
    for (int d = 0; d < OUT_DIM; d++) acc[d] = 0.f;

    for (int kk = 0; kk < IN_DIM / 4; kk++) {
        float4 xv = x4[kk];
#pragma unroll
        for (int d = 0; d < OUT_DIM; d++) {
            float4 wv = W4[d * (IN_DIM / 4) + kk];   // warp-uniform broadcast
            acc[d] += xv.x * wv.x + xv.y * wv.y + xv.z * wv.z + xv.w * wv.w;
        }
    }

    float ss = 0.f, sd = 0.f;
    uint2* newh = (uint2*)(g_newh + ((size_t)n << 6));
#pragma unroll
    for (int j = 0; j < OUT_DIM / 4; j++) {
        float v0 = acc[4*j+0] + sb[4*j+0];
        float v1 = acc[4*j+1] + sb[4*j+1];
        float v2 = acc[4*j+2] + sb[4*j+2];
        float v3 = acc[4*j+3] + sb[4*j+3];
        __half2 h0 = __float22half2_rn(make_float2(v0, v1));
        __half2 h1 = __float22half2_rn(make_float2(v2, v3));
        uint2 hv;
        hv.x = *(unsigned int*)&h0;
        hv.y = *(unsigned int*)&h1;
        newh[j] = hv;
        ss += v0*sas[4*j+0] + v1*sas[4*j+1] + v2*sas[4*j+2] + v3*sas[4*j+3];
        sd += v0*sad[4*j+0] + v1*sad[4*j+1] + v2*sad[4*j+2] + v3*sad[4*j+3];
    }
    g_ssrc[n] = ss;
    g_sdst[n] = sd;
}

// ---------------------------------------------------------------------------
// Kernel 2: exclusive scan of g_cnt -> g_base, decoupled lookback.
// ---------------------------------------------------------------------------
__global__ __launch_bounds__(SCAN_BLK) void k_scan(int nN)
{
    __shared__ int swarp[32];
    __shared__ int s_total;
    __shared__ int s_boff;
    int tid  = threadIdx.x;
    int lane = tid & 31;
    int wid  = tid >> 5;
    int bid  = blockIdx.x;
    int i    = bid * SCAN_BLK + tid;

    int v = (i < nN) ? g_cnt[i] : 0;

    int inc = v;
#pragma unroll
    for (int off = 1; off < 32; off <<= 1) {
        int t = __shfl_up_sync(0xFFFFFFFF, inc, off);
        if (lane >= off) inc += t;
    }
    if (lane == 31) swarp[wid] = inc;
    __syncthreads();
    if (wid == 0) {
        int wv = swarp[lane];
        int winc = wv;
#pragma unroll
        for (int off = 1; off < 32; off <<= 1) {
            int t = __shfl_up_sync(0xFFFFFFFF, winc, off);
            if (lane >= off) winc += t;
        }
        swarp[lane] = winc - wv;
    }
    __syncthreads();
    int incl = swarp[wid] + inc;
    if (tid == SCAN_BLK - 1) s_total = incl;
    __syncthreads();

    if (tid == 0) {
        g_bsum[bid] = s_total;
        __threadfence();
        *(volatile int*)&g_flag[bid] = 1;
    }

    if (wid == 0) {
        int off = 0;
        for (int base = 0; base < bid; base += 32) {
            int j = base + lane;
            int vj = 0;
            if (j < bid) {
                while (*(volatile int*)&g_flag[j] == 0) {}
                __threadfence();
                vj = *(volatile int*)&g_bsum[j];
            }
#pragma unroll
            for (int o = 16; o > 0; o >>= 1)
                vj += __shfl_down_sync(0xFFFFFFFF, vj, o);
            off += __shfl_sync(0xFFFFFFFF, vj, 0);
        }
        if (lane == 0) s_boff = off;
    }
    __syncthreads();

    if (i < nN) g_base[i] = s_boff + incl - v;
}

// ---------------------------------------------------------------------------
// Kernel 3: place dst (4B) into CSR slot — no gathers, no exp here.
// Cursor atomic leaves g_base[n] == end[n].
// ---------------------------------------------------------------------------
__global__ __launch_bounds__(256) void k_place(
    const int* __restrict__ eidx, int nE, int nN)
{
    int e = blockIdx.x * blockDim.x + threadIdx.x;
    if (e >= nE) return;
    int s = eidx[e];
    int d = eidx[(size_t)nE + e];
    s = min(max(s, 0), nN - 1);
    d = min(max(d, 0), nN - 1);
    int pos = atomicAdd(&g_base[s], 1);
    g_csr[pos] = d;
}

// ---------------------------------------------------------------------------
// Kernel 4: gather-aggregate + normalize. 8 lanes/node, lane c owns 16B of
// the fp16 row. Score/exp recomputed here (issued once per warp-inst);
// sdst[dst] is a broadcast load within a group. Unrolled x4 for MLP.
// Re-zeroes g_cnt for replay.
// ---------------------------------------------------------------------------
__global__ __launch_bounds__(256) void k_aggregate(
    float* __restrict__ out, int nN)
{
    int n = blockIdx.x * 32 + (threadIdx.x >> 3);
    int c = threadIdx.x & 7;
    if (n >= nN) return;

    int beg = (n == 0) ? 0 : g_base[n - 1];
    int end = g_base[n];
    float ssn = g_ssrc[n];

    float acc[8];
#pragma unroll
    for (int j = 0; j < 8; j++) acc[j] = 0.f;
    float rs = 0.f;

    int i = beg;
    for (; i + 4 <= end; i += 4) {
        int dst0 = g_csr[i];
        int dst1 = g_csr[i + 1];
        int dst2 = g_csr[i + 2];
        int dst3 = g_csr[i + 3];
        float sd0 = g_sdst[dst0];
        float sd1 = g_sdst[dst1];
        float sd2 = g_sdst[dst2];
        float sd3 = g_sdst[dst3];
        uint4 h0 = *(const uint4*)(g_newh + ((size_t)dst0 << 6) + c * 8);
        uint4 h1 = *(const uint4*)(g_newh + ((size_t)dst1 << 6) + c * 8);
        uint4 h2 = *(const uint4*)(g_newh + ((size_t)dst2 << 6) + c * 8);
        uint4 h3 = *(const uint4*)(g_newh + ((size_t)dst3 << 6) + c * 8);
        float sc0 = ssn + sd0;  sc0 = sc0 > 0.f ? sc0 : SLOPE * sc0;
        float sc1 = ssn + sd1;  sc1 = sc1 > 0.f ? sc1 : SLOPE * sc1;
        float sc2 = ssn + sd2;  sc2 = sc2 > 0.f ? sc2 : SLOPE * sc2;
        float sc3 = ssn + sd3;  sc3 = sc3 > 0.f ? sc3 : SLOPE * sc3;
        float ev0 = __expf(sc0);
        float ev1 = __expf(sc1);
        float ev2 = __expf(sc2);
        float ev3 = __expf(sc3);
#pragma unroll
        for (int q = 0; q < 4; q++) {
            float ev = (q == 0) ? ev0 : (q == 1) ? ev1 : (q == 2) ? ev2 : ev3;
            uint4 hv = (q == 0) ? h0 : (q == 1) ? h1 : (q == 2) ? h2 : h3;
            float2 f0 = __half22float2(*(__half2*)&hv.x);
            float2 f1 = __half22float2(*(__half2*)&hv.y);
            float2 f2 = __half22float2(*(__half2*)&hv.z);
            float2 f3 = __half22float2(*(__half2*)&hv.w);
            acc[0] += ev * f0.x;  acc[1] += ev * f0.y;
            acc[2] += ev * f1.x;  acc[3] += ev * f1.y;
            acc[4] += ev * f2.x;  acc[5] += ev * f2.y;
            acc[6] += ev * f3.x;  acc[7] += ev * f3.y;
            rs += ev;
        }
    }
    for (; i < end; i++) {
        int dst = g_csr[i];
        float sc = ssn + g_sdst[dst];
        sc = sc > 0.f ? sc : SLOPE * sc;
        float ev = __expf(sc);
        uint4 hv = *(const uint4*)(g_newh + ((size_t)dst << 6) + c * 8);
        float2 f0 = __half22float2(*(__half2*)&hv.x);
        float2 f1 = __half22float2(*(__half2*)&hv.y);
        float2 f2 = __half22float2(*(__half2*)&hv.z);
        float2 f3 = __half22float2(*(__half2*)&hv.w);
        acc[0] += ev * f0.x;  acc[1] += ev * f0.y;
        acc[2] += ev * f1.x;  acc[3] += ev * f1.y;
        acc[4] += ev * f2.x;  acc[5] += ev * f2.y;
        acc[6] += ev * f3.x;  acc[7] += ev * f3.y;
        rs += ev;
    }

    float inv = 1.f / (rs + EPS);
    float* op = out + ((size_t)n << 6) + c * 8;
    *(float4*)op       = make_float4(acc[0]*inv, acc[1]*inv, acc[2]*inv, acc[3]*inv);
    *(float4*)(op + 4) = make_float4(acc[4]*inv, acc[5]*inv, acc[6]*inv, acc[7]*inv);

    if (c == 0) g_cnt[n] = 0;   // clean for next launch (graph replay)
}

// ---------------------------------------------------------------------------
extern "C" void kernel_launch(void* const* d_in, const int* in_sizes, int n_in,
                              void* d_out, int out_size)
{
    const float* x    = (const float*)d_in[0];
    const int*   eidx = (const int*)d_in[1];    // int32 (JAX x64 disabled)
    const float* W    = (const float*)d_in[2];
    const float* b    = (const float*)d_in[3];
    const float* a    = (const float*)d_in[4];
    float* out = (float*)d_out;

    int nN = in_sizes[0] / IN_DIM;   // 50000
    int nE = in_sizes[1] / 2;        // 1600000

    int nbT = (nN + 127) / 128;      // 391 transform blocks (128 thr, 1 node/thr)
    int nbH = 2048;                  // histogram blocks (128 thr, grid-stride)
    k_fused<<<nbT + nbH, 128>>>(x, W, b, a, eidx, nN, nE, nbT);

    int nbS = (nN + SCAN_BLK - 1) / SCAN_BLK;     // 49
    k_scan<<<nbS, SCAN_BLK>>>(nN);

    k_place<<<(nE + 255) / 256, 256>>>(eidx, nE, nN);

    k_aggregate<<<(nN + 31) / 32, 256>>>(out, nN);
}

// round 14
// speedup vs baseline: 1.1549x; 1.0708x over previous
#include <cuda_runtime.h>
#include <cuda_fp16.h>
#include <cstdint>

#define IN_DIM 128
#define OUT_DIM 64
#define MAXN 50000
#define MAXE 1600000
#define SLOPE 0.1f
#define EPS 1e-12f
#define SCAN_BLK 1024
#define MAX_SCAN_BLOCKS 64
#define XF_BLOCKS_L1 98                 // transform blocks riding with hist
#define XF_SPLIT (XF_BLOCKS_L1 * 256)   // = 25088 nodes in launch 1

// Scratch (static device globals — allocation is forbidden). Zero-init at load.
__device__ __align__(256) __half g_newh[MAXN * OUT_DIM]; // transformed features, fp16
__device__ float  g_ssrc[MAXN];          // new[n] . a_src
__device__ float  g_sdst[MAXN];          // new[n] . a_dst
__device__ int    g_cnt[MAXN];           // out-degree histogram (zeroed by k_aggregate)
__device__ int    g_base[MAXN];          // CSR offsets (mutated by k_place into end[])
__device__ int    g_csr[MAXE];           // src-sorted dst indices (4B payload)
__device__ int    g_bsum[MAX_SCAN_BLOCKS];
__device__ int    g_flag[MAX_SCAN_BLOCKS];

// ---------------------------------------------------------------------------
// Transform body (proven R10 form): one node per thread, warp-uniform W
// broadcast from smem. Used by both mixed launches on disjoint node ranges.
// ---------------------------------------------------------------------------
__device__ __forceinline__ void transform_body(
    const float* __restrict__ x, const float* __restrict__ W,
    const float* __restrict__ b, const float* __restrict__ a,
    int n, int nN)
{
    __shared__ __align__(16) float sW[OUT_DIM * IN_DIM];
    __shared__ float sb[OUT_DIM], sas[OUT_DIM], sad[OUT_DIM];
    for (int i = threadIdx.x; i < OUT_DIM * IN_DIM; i += blockDim.x) sW[i] = W[i];
    if (threadIdx.x < OUT_DIM) {
        sb[threadIdx.x]  = b[threadIdx.x];
        sas[threadIdx.x] = a[threadIdx.x];
        sad[threadIdx.x] = a[OUT_DIM + threadIdx.x];
    }
    __syncthreads();

    if (n >= nN) return;

    const float4* __restrict__ x4 = (const float4*)(x + (size_t)n * IN_DIM);
    const float4* __restrict__ W4 = (const float4*)sW;

    float acc[OUT_DIM];
#pragma unroll
    for (int d = 0; d < OUT_DIM; d++) acc[d] = 0.f;

    for (int kk = 0; kk < IN_DIM / 4; kk++) {
        float4 xv = x4[kk];
#pragma unroll
        for (int d = 0; d < OUT_DIM; d++) {
            float4 wv = W4[d * (IN_DIM / 4) + kk];   // warp-uniform broadcast
            acc[d] += xv.x * wv.x + xv.y * wv.y + xv.z * wv.z + xv.w * wv.w;
        }
    }

    float ss = 0.f, sd = 0.f;
    uint2* newh = (uint2*)(g_newh + ((size_t)n << 6));
#pragma unroll
    for (int j = 0; j < OUT_DIM / 4; j++) {
        float v0 = acc[4*j+0] + sb[4*j+0];
        float v1 = acc[4*j+1] + sb[4*j+1];
        float v2 = acc[4*j+2] + sb[4*j+2];
        float v3 = acc[4*j+3] + sb[4*j+3];
        __half2 h0 = __float22half2_rn(make_float2(v0, v1));
        __half2 h1 = __float22half2_rn(make_float2(v2, v3));
        uint2 hv;
        hv.x = *(unsigned int*)&h0;
        hv.y = *(unsigned int*)&h1;
        newh[j] = hv;
        ss += v0*sas[4*j+0] + v1*sas[4*j+1] + v2*sas[4*j+2] + v3*sas[4*j+3];
        sd += v0*sad[4*j+0] + v1*sad[4*j+1] + v2*sad[4*j+2] + v3*sad[4*j+3];
    }
    g_ssrc[n] = ss;
    g_sdst[n] = sd;
}

// ---------------------------------------------------------------------------
// Launch 1: blocks [0, XF_BLOCKS_L1): transform nodes [0, XF_SPLIT).
//           blocks [XF_BLOCKS_L1, ...): histogram of src (grid-stride).
//           Block 0 zeroes scan flags.
// ---------------------------------------------------------------------------
__global__ __launch_bounds__(256) void k_hist_xf(
    const float* __restrict__ x, const float* __restrict__ W,
    const float* __restrict__ b, const float* __restrict__ a,
    const int* __restrict__ eidx, int nN, int nE)
{
    if ((int)blockIdx.x >= XF_BLOCKS_L1) {
        int tidg   = (blockIdx.x - XF_BLOCKS_L1) * blockDim.x + threadIdx.x;
        int stride = (gridDim.x - XF_BLOCKS_L1) * blockDim.x;
        for (int e = tidg; e < nE; e += stride) {
            int s = eidx[e];
            s = min(max(s, 0), nN - 1);
            atomicAdd(&g_cnt[s], 1);
        }
        return;
    }
    if (blockIdx.x == 0 && threadIdx.x < MAX_SCAN_BLOCKS) g_flag[threadIdx.x] = 0;
    int n = blockIdx.x * 256 + threadIdx.x;          // < XF_SPLIT <= nN
    transform_body(x, W, b, a, n, nN);
}

// ---------------------------------------------------------------------------
// Kernel 2: exclusive scan of g_cnt -> g_base, decoupled lookback.
// ---------------------------------------------------------------------------
__global__ __launch_bounds__(SCAN_BLK) void k_scan(int nN)
{
    __shared__ int swarp[32];
    __shared__ int s_total;
    __shared__ int s_boff;
    int tid  = threadIdx.x;
    int lane = tid & 31;
    int wid  = tid >> 5;
    int bid  = blockIdx.x;
    int i    = bid * SCAN_BLK + tid;

    int v = (i < nN) ? g_cnt[i] : 0;

    int inc = v;
#pragma unroll
    for (int off = 1; off < 32; off <<= 1) {
        int t = __shfl_up_sync(0xFFFFFFFF, inc, off);
        if (lane >= off) inc += t;
    }
    if (lane == 31) swarp[wid] = inc;
    __syncthreads();
    if (wid == 0) {
        int wv = swarp[lane];
        int winc = wv;
#pragma unroll
        for (int off = 1; off < 32; off <<= 1) {
            int t = __shfl_up_sync(0xFFFFFFFF, winc, off);
            if (lane >= off) winc += t;
        }
        swarp[lane] = winc - wv;
    }
    __syncthreads();
    int incl = swarp[wid] + inc;
    if (tid == SCAN_BLK - 1) s_total = incl;
    __syncthreads();

    if (tid == 0) {
        g_bsum[bid] = s_total;
        __threadfence();
        *(volatile int*)&g_flag[bid] = 1;
    }

    if (wid == 0) {
        int off = 0;
        for (int base = 0; base < bid; base += 32) {
            int j = base + lane;
            int vj = 0;
            if (j < bid) {
                while (*(volatile int*)&g_flag[j] == 0) {}
                __threadfence();
                vj = *(volatile int*)&g_bsum[j];
            }
#pragma unroll
            for (int o = 16; o > 0; o >>= 1)
                vj += __shfl_down_sync(0xFFFFFFFF, vj, o);
            off += __shfl_sync(0xFFFFFFFF, vj, 0);
        }
        if (lane == 0) s_boff = off;
    }
    __syncthreads();

    if (i < nN) g_base[i] = s_boff + incl - v;
}

// ---------------------------------------------------------------------------
// Launch 3: blocks [0, nbX): transform nodes [XF_SPLIT, nN).
//           blocks [nbX, ...): place dst into CSR slot (1 edge/thread).
//           (place only needs eidx + g_base; transform output is consumed
//            first by k_aggregate, so this overlap is dependence-safe.)
// ---------------------------------------------------------------------------
__global__ __launch_bounds__(256) void k_place_xf(
    const float* __restrict__ x, const float* __restrict__ W,
    const float* __restrict__ b, const float* __restrict__ a,
    const int* __restrict__ eidx, int nN, int nE, int nbX)
{
    if ((int)blockIdx.x >= nbX) {
        int e = (blockIdx.x - nbX) * blockDim.x + threadIdx.x;
        if (e >= nE) return;
        int s = eidx[e];
        int d = eidx[(size_t)nE + e];
        s = min(max(s, 0), nN - 1);
        d = min(max(d, 0), nN - 1);
        int pos = atomicAdd(&g_base[s], 1);
        g_csr[pos] = d;
        return;
    }
    int n = XF_SPLIT + blockIdx.x * 256 + threadIdx.x;
    transform_body(x, W, b, a, n, nN);
}

// ---------------------------------------------------------------------------
// Kernel 4: gather-aggregate + normalize (verified R10 form). 8 lanes/node,
// lane c owns 16B of the fp16 row; score/exp recomputed per warp-inst;
// unrolled x4 for MLP. Re-zeroes g_cnt for replay.
// ---------------------------------------------------------------------------
__global__ __launch_bounds__(256) void k_aggregate(
    float* __restrict__ out, int nN)
{
    int n = blockIdx.x * 32 + (threadIdx.x >> 3);
    int c = threadIdx.x & 7;
    if (n >= nN) return;

    int beg = (n == 0) ? 0 : g_base[n - 1];
    int end = g_base[n];
    float ssn = g_ssrc[n];

    float acc[8];
#pragma unroll
    for (int j = 0; j < 8; j++) acc[j] = 0.f;
    float rs = 0.f;

    int i = beg;
    for (; i + 4 <= end; i += 4) {
        int dst0 = g_csr[i];
        int dst1 = g_csr[i + 1];
        int dst2 = g_csr[i + 2];
        int dst3 = g_csr[i + 3];
        float sd0 = g_sdst[dst0];
        float sd1 = g_sdst[dst1];
        float sd2 = g_sdst[dst2];
        float sd3 = g_sdst[dst3];
        uint4 h0 = *(const uint4*)(g_newh + ((size_t)dst0 << 6) + c * 8);
        uint4 h1 = *(const uint4*)(g_newh + ((size_t)dst1 << 6) + c * 8);
        uint4 h2 = *(const uint4*)(g_newh + ((size_t)dst2 << 6) + c * 8);
        uint4 h3 = *(const uint4*)(g_newh + ((size_t)dst3 << 6) + c * 8);
        float sc0 = ssn + sd0;  sc0 = sc0 > 0.f ? sc0 : SLOPE * sc0;
        float sc1 = ssn + sd1;  sc1 = sc1 > 0.f ? sc1 : SLOPE * sc1;
        float sc2 = ssn + sd2;  sc2 = sc2 > 0.f ? sc2 : SLOPE * sc2;
        float sc3 = ssn + sd3;  sc3 = sc3 > 0.f ? sc3 : SLOPE * sc3;
        float ev0 = __expf(sc0);
        float ev1 = __expf(sc1);
        float ev2 = __expf(sc2);
        float ev3 = __expf(sc3);
#pragma unroll
        for (int q = 0; q < 4; q++) {
            float ev = (q == 0) ? ev0 : (q == 1) ? ev1 : (q == 2) ? ev2 : ev3;
            uint4 hv = (q == 0) ? h0 : (q == 1) ? h1 : (q == 2) ? h2 : h3;
            float2 f0 = __half22float2(*(__half2*)&hv.x);
            float2 f1 = __half22float2(*(__half2*)&hv.y);
            float2 f2 = __half22float2(*(__half2*)&hv.z);
            float2 f3 = __half22float2(*(__half2*)&hv.w);
            acc[0] += ev * f0.x;  acc[1] += ev * f0.y;
            acc[2] += ev * f1.x;  acc[3] += ev * f1.y;
            acc[4] += ev * f2.x;  acc[5] += ev * f2.y;
            acc[6] += ev * f3.x;  acc[7] += ev * f3.y;
            rs += ev;
        }
    }
    for (; i < end; i++) {
        int dst = g_csr[i];
        float sc = ssn + g_sdst[dst];
        sc = sc > 0.f ? sc : SLOPE * sc;
        float ev = __expf(sc);
        uint4 hv = *(const uint4*)(g_newh + ((size_t)dst << 6) + c * 8);
        float2 f0 = __half22float2(*(__half2*)&hv.x);
        float2 f1 = __half22float2(*(__half2*)&hv.y);
        float2 f2 = __half22float2(*(__half2*)&hv.z);
        float2 f3 = __half22float2(*(__half2*)&hv.w);
        acc[0] += ev * f0.x;  acc[1] += ev * f0.y;
        acc[2] += ev * f1.x;  acc[3] += ev * f1.y;
        acc[4] += ev * f2.x;  acc[5] += ev * f2.y;
        acc[6] += ev * f3.x;  acc[7] += ev * f3.y;
        rs += ev;
    }

    float inv = 1.f / (rs + EPS);
    float* op = out + ((size_t)n << 6) + c * 8;
    *(float4*)op       = make_float4(acc[0]*inv, acc[1]*inv, acc[2]*inv, acc[3]*inv);
    *(float4*)(op + 4) = make_float4(acc[4]*inv, acc[5]*inv, acc[6]*inv, acc[7]*inv);

    if (c == 0) g_cnt[n] = 0;   // clean for next launch (graph replay)
}

// ---------------------------------------------------------------------------
extern "C" void kernel_launch(void* const* d_in, const int* in_sizes, int n_in,
                              void* d_out, int out_size)
{
    const float* x    = (const float*)d_in[0];
    const int*   eidx = (const int*)d_in[1];    // int32 (JAX x64 disabled)
    const float* W    = (const float*)d_in[2];
    const float* b    = (const float*)d_in[3];
    const float* a    = (const float*)d_in[4];
    float* out = (float*)d_out;

    int nN = in_sizes[0] / IN_DIM;   // 50000
    int nE = in_sizes[1] / 2;        // 1600000

    // L1: transform first 25088 nodes + full histogram
    int nbH = 1024;
    k_hist_xf<<<XF_BLOCKS_L1 + nbH, 256>>>(x, W, b, a, eidx, nN, nE);

    // L2: scan
    int nbS = (nN + SCAN_BLK - 1) / SCAN_BLK;     // 49
    k_scan<<<nbS, SCAN_BLK>>>(nN);

    // L3: transform remaining nodes + place
    int nbX = (nN - XF_SPLIT + 255) / 256;        // 98
    int nbP = (nE + 255) / 256;                   // 6250
    k_place_xf<<<nbX + nbP, 256>>>(x, W, b, a, eidx, nN, nE, nbX);

    // L4: aggregate
    k_aggregate<<<(nN + 31) / 32, 256>>>(out, nN);
}

// round 15
// speedup vs baseline: 1.3760x; 1.1914x over previous
#include <cuda_runtime.h>
#include <cuda_fp16.h>
#include <cstdint>

#define IN_DIM 128
#define OUT_DIM 64
#define MAXN 50000
#define MAXE 1600000
#define SLOPE 0.1f
#define EPS 1e-12f
#define SCAN_BLK 1024
#define MAX_SCAN_BLOCKS 64

// Scratch (static device globals — allocation is forbidden). Zero-init at load.
__device__ __align__(256) __half g_newh[MAXN * OUT_DIM]; // transformed features, fp16
__device__ float  g_ssrc[MAXN];          // new[n] . a_src
__device__ float  g_sdst[MAXN];          // new[n] . a_dst
__device__ int    g_cnt[MAXN];           // out-degree histogram (zeroed by k_aggregate)
__device__ int    g_base[MAXN];          // CSR offsets (mutated by k_place into end[])
__device__ int    g_csr[MAXE];           // src-sorted dst indices (4B payload)
__device__ int    g_bsum[MAX_SCAN_BLOCKS];
__device__ int    g_flag[MAX_SCAN_BLOCKS];

// ---------------------------------------------------------------------------
// Kernel A (stream A): transform new = x@W^T+b -> fp16, scores.
// Proven R4/R10 form: one node/thread, warp-uniform W broadcast from smem.
// Runs CONCURRENTLY with the hist->scan->place chain (its outputs are only
// consumed by k_aggregate).
// ---------------------------------------------------------------------------
__global__ __launch_bounds__(256) void k_transform(
    const float* __restrict__ x, const float* __restrict__ W,
    const float* __restrict__ b, const float* __restrict__ a, int nN)
{
    __shared__ __align__(16) float sW[OUT_DIM * IN_DIM];
    __shared__ float sb[OUT_DIM], sas[OUT_DIM], sad[OUT_DIM];
    for (int i = threadIdx.x; i < OUT_DIM * IN_DIM; i += blockDim.x) sW[i] = W[i];
    if (threadIdx.x < OUT_DIM) {
        sb[threadIdx.x]  = b[threadIdx.x];
        sas[threadIdx.x] = a[threadIdx.x];
        sad[threadIdx.x] = a[OUT_DIM + threadIdx.x];
    }
    __syncthreads();

    int n = blockIdx.x * blockDim.x + threadIdx.x;
    if (n >= nN) return;

    const float4* __restrict__ x4 = (const float4*)(x + (size_t)n * IN_DIM);
    const float4* __restrict__ W4 = (const float4*)sW;

    float acc[OUT_DIM];
#pragma unroll
    for (int d = 0; d < OUT_DIM; d++) acc[d] = 0.f;

    for (int kk = 0; kk < IN_DIM / 4; kk++) {
        float4 xv = x4[kk];
#pragma unroll
        for (int d = 0; d < OUT_DIM; d++) {
            float4 wv = W4[d * (IN_DIM / 4) + kk];   // warp-uniform broadcast
            acc[d] += xv.x * wv.x + xv.y * wv.y + xv.z * wv.z + xv.w * wv.w;
        }
    }

    float ss = 0.f, sd = 0.f;
    uint2* newh = (uint2*)(g_newh + ((size_t)n << 6));
#pragma unroll
    for (int j = 0; j < OUT_DIM / 4; j++) {
        float v0 = acc[4*j+0] + sb[4*j+0];
        float v1 = acc[4*j+1] + sb[4*j+1];
        float v2 = acc[4*j+2] + sb[4*j+2];
        float v3 = acc[4*j+3] + sb[4*j+3];
        __half2 h0 = __float22half2_rn(make_float2(v0, v1));
        __half2 h1 = __float22half2_rn(make_float2(v2, v3));
        uint2 hv;
        hv.x = *(unsigned int*)&h0;
        hv.y = *(unsigned int*)&h1;
        newh[j] = hv;
        ss += v0*sas[4*j+0] + v1*sas[4*j+1] + v2*sas[4*j+2] + v3*sas[4*j+3];
        sd += v0*sad[4*j+0] + v1*sad[4*j+1] + v2*sad[4*j+2] + v3*sad[4*j+3];
    }
    g_ssrc[n] = ss;
    g_sdst[n] = sd;
}

// ---------------------------------------------------------------------------
// Kernel 1 (main stream): histogram of src; block 0 zeroes scan flags first.
// Standalone -> full occupancy (no fused-transform register tax).
// ---------------------------------------------------------------------------
__global__ __launch_bounds__(256) void k_hist(
    const int* __restrict__ eidx, int nE, int nN)
{
    if (blockIdx.x == 0 && threadIdx.x < MAX_SCAN_BLOCKS) g_flag[threadIdx.x] = 0;
    int e = blockIdx.x * blockDim.x + threadIdx.x;
    if (e >= nE) return;
    int s = eidx[e];
    s = min(max(s, 0), nN - 1);
    atomicAdd(&g_cnt[s], 1);
}

// ---------------------------------------------------------------------------
// Kernel 2: exclusive scan of g_cnt -> g_base, decoupled lookback.
// ---------------------------------------------------------------------------
__global__ __launch_bounds__(SCAN_BLK) void k_scan(int nN)
{
    __shared__ int swarp[32];
    __shared__ int s_total;
    __shared__ int s_boff;
    int tid  = threadIdx.x;
    int lane = tid & 31;
    int wid  = tid >> 5;
    int bid  = blockIdx.x;
    int i    = bid * SCAN_BLK + tid;

    int v = (i < nN) ? g_cnt[i] : 0;

    int inc = v;
#pragma unroll
    for (int off = 1; off < 32; off <<= 1) {
        int t = __shfl_up_sync(0xFFFFFFFF, inc, off);
        if (lane >= off) inc += t;
    }
    if (lane == 31) swarp[wid] = inc;
    __syncthreads();
    if (wid == 0) {
        int wv = swarp[lane];
        int winc = wv;
#pragma unroll
        for (int off = 1; off < 32; off <<= 1) {
            int t = __shfl_up_sync(0xFFFFFFFF, winc, off);
            if (lane >= off) winc += t;
        }
        swarp[lane] = winc - wv;
    }
    __syncthreads();
    int incl = swarp[wid] + inc;
    if (tid == SCAN_BLK - 1) s_total = incl;
    __syncthreads();

    if (tid == 0) {
        g_bsum[bid] = s_total;
        __threadfence();
        *(volatile int*)&g_flag[bid] = 1;
    }

    if (wid == 0) {
        int off = 0;
        for (int base = 0; base < bid; base += 32) {
            int j = base + lane;
            int vj = 0;
            if (j < bid) {
                while (*(volatile int*)&g_flag[j] == 0) {}
                __threadfence();
                vj = *(volatile int*)&g_bsum[j];
            }
#pragma unroll
            for (int o = 16; o > 0; o >>= 1)
                vj += __shfl_down_sync(0xFFFFFFFF, vj, o);
            off += __shfl_sync(0xFFFFFFFF, vj, 0);
        }
        if (lane == 0) s_boff = off;
    }
    __syncthreads();

    if (i < nN) g_base[i] = s_boff + incl - v;
}

// ---------------------------------------------------------------------------
// Kernel 3: place dst (4B) into CSR slot. Cursor atomic leaves g_base[n]==end.
// Standalone -> 18 regs, full occupancy.
// ---------------------------------------------------------------------------
__global__ __launch_bounds__(256) void k_place(
    const int* __restrict__ eidx, int nE, int nN)
{
    int e = blockIdx.x * blockDim.x + threadIdx.x;
    if (e >= nE) return;
    int s = eidx[e];
    int d = eidx[(size_t)nE + e];
    s = min(max(s, 0), nN - 1);
    d = min(max(d, 0), nN - 1);
    int pos = atomicAdd(&g_base[s], 1);
    g_csr[pos] = d;
}

// ---------------------------------------------------------------------------
// Kernel 4: gather-aggregate + normalize (verified R10 form). 8 lanes/node,
// lane c owns 16B of the fp16 row; score/exp recomputed per warp-inst;
// unrolled x4 for MLP. Re-zeroes g_cnt for replay.
// ---------------------------------------------------------------------------
__global__ __launch_bounds__(256) void k_aggregate(
    float* __restrict__ out, int nN)
{
    int n = blockIdx.x * 32 + (threadIdx.x >> 3);
    int c = threadIdx.x & 7;
    if (n >= nN) return;

    int beg = (n == 0) ? 0 : g_base[n - 1];
    int end = g_base[n];
    float ssn = g_ssrc[n];

    float acc[8];
#pragma unroll
    for (int j = 0; j < 8; j++) acc[j] = 0.f;
    float rs = 0.f;

    int i = beg;
    for (; i + 4 <= end; i += 4) {
        int dst0 = g_csr[i];
        int dst1 = g_csr[i + 1];
        int dst2 = g_csr[i + 2];
        int dst3 = g_csr[i + 3];
        float sd0 = g_sdst[dst0];
        float sd1 = g_sdst[dst1];
        float sd2 = g_sdst[dst2];
        float sd3 = g_sdst[dst3];
        uint4 h0 = *(const uint4*)(g_newh + ((size_t)dst0 << 6) + c * 8);
        uint4 h1 = *(const uint4*)(g_newh + ((size_t)dst1 << 6) + c * 8);
        uint4 h2 = *(const uint4*)(g_newh + ((size_t)dst2 << 6) + c * 8);
        uint4 h3 = *(const uint4*)(g_newh + ((size_t)dst3 << 6) + c * 8);
        float sc0 = ssn + sd0;  sc0 = sc0 > 0.f ? sc0 : SLOPE * sc0;
        float sc1 = ssn + sd1;  sc1 = sc1 > 0.f ? sc1 : SLOPE * sc1;
        float sc2 = ssn + sd2;  sc2 = sc2 > 0.f ? sc2 : SLOPE * sc2;
        float sc3 = ssn + sd3;  sc3 = sc3 > 0.f ? sc3 : SLOPE * sc3;
        float ev0 = __expf(sc0);
        float ev1 = __expf(sc1);
        float ev2 = __expf(sc2);
        float ev3 = __expf(sc3);
#pragma unroll
        for (int q = 0; q < 4; q++) {
            float ev = (q == 0) ? ev0 : (q == 1) ? ev1 : (q == 2) ? ev2 : ev3;
            uint4 hv = (q == 0) ? h0 : (q == 1) ? h1 : (q == 2) ? h2 : h3;
            float2 f0 = __half22float2(*(__half2*)&hv.x);
            float2 f1 = __half22float2(*(__half2*)&hv.y);
            float2 f2 = __half22float2(*(__half2*)&hv.z);
            float2 f3 = __half22float2(*(__half2*)&hv.w);
            acc[0] += ev * f0.x;  acc[1] += ev * f0.y;
            acc[2] += ev * f1.x;  acc[3] += ev * f1.y;
            acc[4] += ev * f2.x;  acc[5] += ev * f2.y;
            acc[6] += ev * f3.x;  acc[7] += ev * f3.y;
            rs += ev;
        }
    }
    for (; i < end; i++) {
        int dst = g_csr[i];
        float sc = ssn + g_sdst[dst];
        sc = sc > 0.f ? sc : SLOPE * sc;
        float ev = __expf(sc);
        uint4 hv = *(const uint4*)(g_newh + ((size_t)dst << 6) + c * 8);
        float2 f0 = __half22float2(*(__half2*)&hv.x);
        float2 f1 = __half22float2(*(__half2*)&hv.y);
        float2 f2 = __half22float2(*(__half2*)&hv.z);
        float2 f3 = __half22float2(*(__half2*)&hv.w);
        acc[0] += ev * f0.x;  acc[1] += ev * f0.y;
        acc[2] += ev * f1.x;  acc[3] += ev * f1.y;
        acc[4] += ev * f2.x;  acc[5] += ev * f2.y;
        acc[6] += ev * f3.x;  acc[7] += ev * f3.y;
        rs += ev;
    }

    float inv = 1.f / (rs + EPS);
    float* op = out + ((size_t)n << 6) + c * 8;
    *(float4*)op       = make_float4(acc[0]*inv, acc[1]*inv, acc[2]*inv, acc[3]*inv);
    *(float4*)(op + 4) = make_float4(acc[4]*inv, acc[5]*inv, acc[6]*inv, acc[7]*inv);

    if (c == 0) g_cnt[n] = 0;   // clean for next launch (graph replay)
}

// ---------------------------------------------------------------------------
// Launch topology (fork/join across streams so transform overlaps the whole
// hist->scan->place chain with BOTH sides at their own optimal occupancy):
//
//   main: [e0]----hist----scan----place----[wait eA]--aggregate
//   sA:   [wait e0]------transform------[eA]
//
// Streams/events are created once (host objects only — no device memory).
// ---------------------------------------------------------------------------
extern "C" void kernel_launch(void* const* d_in, const int* in_sizes, int n_in,
                              void* d_out, int out_size)
{
    const float* x    = (const float*)d_in[0];
    const int*   eidx = (const int*)d_in[1];    // int32 (JAX x64 disabled)
    const float* W    = (const float*)d_in[2];
    const float* b    = (const float*)d_in[3];
    const float* a    = (const float*)d_in[4];
    float* out = (float*)d_out;

    int nN = in_sizes[0] / IN_DIM;   // 50000
    int nE = in_sizes[1] / 2;        // 1600000

    static cudaStream_t sA = nullptr;
    static cudaEvent_t  e0 = nullptr, eA = nullptr;
    if (sA == nullptr) {
        cudaStreamCreateWithFlags(&sA, cudaStreamNonBlocking);
        cudaEventCreateWithFlags(&e0, cudaEventDisableTiming);
        cudaEventCreateWithFlags(&eA, cudaEventDisableTiming);
    }

    // fork: transform on sA
    cudaEventRecord(e0, 0);
    cudaStreamWaitEvent(sA, e0, 0);
    k_transform<<<(nN + 255) / 256, 256, 0, sA>>>(x, W, b, a, nN);
    cudaEventRecord(eA, sA);

    // main chain: hist -> scan -> place
    k_hist<<<(nE + 255) / 256, 256>>>(eidx, nE, nN);
    int nbS = (nN + SCAN_BLK - 1) / SCAN_BLK;     // 49
    k_scan<<<nbS, SCAN_BLK>>>(nN);
    k_place<<<(nE + 255) / 256, 256>>>(eidx, nE, nN);

    // join: aggregate needs transform outputs too
    cudaStreamWaitEvent(0, eA, 0);
    k_aggregate<<<(nN + 31) / 32, 256>>>(out, nN);
}